// round 6
// baseline (speedup 1.0000x reference)
#include <cuda_runtime.h>
#include <cuda_bf16.h>
#include <stdint.h>
#include <math.h>

// Problem constants
#define BATCH 2
#define SEQ   2048
#define EMB   1024
#define NHEAD 16
#define HDIM  64
#define MROWS (BATCH * SEQ)      // 4096
#define ATTN_SCALE 0.125f        // 1/sqrt(64)
#define NKS (EMB / 32)           // 32 k-steps

typedef unsigned long long u64;

// ---------------------------------------------------------------------------
// Scratch (allocation-free rule: __device__ globals)
// ---------------------------------------------------------------------------
__device__ float g_Q[MROWS * EMB];
__device__ float g_K[MROWS * EMB];
__device__ float g_V[MROWS * EMB];
__device__ float g_A[MROWS * EMB];
__device__ float g_RX[MROWS * EMB];   // tf32-rounded activation input
__device__ float g_RW[EMB * EMB];     // tf32-rounded weight

// ---------------------------------------------------------------------------
// helpers
// ---------------------------------------------------------------------------
__device__ __forceinline__ uint32_t f2tf32(float x) {
    uint32_t u;
    asm("cvt.rna.tf32.f32 %0, %1;" : "=r"(u) : "f"(x));
    return u;
}
__device__ __forceinline__ float tf32r(float x) { return __uint_as_float(f2tf32(x)); }

__device__ __forceinline__ void mma8(float* c, const uint32_t* a, const uint32_t* b) {
    asm volatile(
        "mma.sync.aligned.m16n8k8.row.col.f32.tf32.tf32.f32 "
        "{%0,%1,%2,%3}, {%4,%5,%6,%7}, {%8,%9}, {%0,%1,%2,%3};"
        : "+f"(c[0]), "+f"(c[1]), "+f"(c[2]), "+f"(c[3])
        : "r"(a[0]), "r"(a[1]), "r"(a[2]), "r"(a[3]), "r"(b[0]), "r"(b[1]));
}

__device__ __forceinline__ void cpa16(uint32_t s, const void* g) {
    asm volatile("cp.async.cg.shared.global [%0], [%1], 16;\n" :: "r"(s), "l"(g));
}
#define CP_COMMIT() asm volatile("cp.async.commit_group;\n" ::: "memory")
#define CP_WAIT2()  asm volatile("cp.async.wait_group 2;\n"  ::: "memory")

__device__ __forceinline__ void ldsm4(uint32_t& r0, uint32_t& r1, uint32_t& r2,
                                      uint32_t& r3, uint32_t addr) {
    asm volatile("ldmatrix.sync.aligned.m8n8.x4.shared.b16 {%0,%1,%2,%3}, [%4];"
                 : "=r"(r0), "=r"(r1), "=r"(r2), "=r"(r3) : "r"(addr));
}

// packed fp32x2 (sm_100+ double-rate fp32 path)
__device__ __forceinline__ u64 fma2(u64 a, u64 b, u64 c) {
    u64 d;
    asm("fma.rn.f32x2 %0, %1, %2, %3;" : "=l"(d) : "l"(a), "l"(b), "l"(c));
    return d;
}
__device__ __forceinline__ u64 mul2(u64 a, u64 b) {
    u64 d;
    asm("mul.rn.f32x2 %0, %1, %2;" : "=l"(d) : "l"(a), "l"(b));
    return d;
}
__device__ __forceinline__ u64 pack2(float lo, float hi) {
    u64 d;
    asm("mov.b64 %0, {%1, %2};" : "=l"(d) : "f"(lo), "f"(hi));
    return d;
}
__device__ __forceinline__ void unpack2(u64 v, float& lo, float& hi) {
    asm("mov.b64 {%0, %1}, %2;" : "=f"(lo), "=f"(hi) : "l"(v));
}

// ---------------------------------------------------------------------------
// tf32 rounding pre-pass (elementwise, vectorized)
// ---------------------------------------------------------------------------
__global__ void __launch_bounds__(256)
round_tf32_kernel(const float4* __restrict__ in, float4* __restrict__ out)
{
    int i = blockIdx.x * 256 + threadIdx.x;
    float4 v = in[i];
    v.x = tf32r(v.x); v.y = tf32r(v.y); v.z = tf32r(v.z); v.w = tf32r(v.w);
    out[i] = v;
}

// ---------------------------------------------------------------------------
// GEMM: C[4096,1024] = A @ W^T + bias. Inputs pre-rounded to tf32.
// CTA 128x128, k-step 32. 3-stage cp.async pipeline, SW128 swizzled SMEM,
// ldmatrix fragment loads, mma.m16n8k8.tf32. launch_bounds (256,2) so two
// CTAs fit per SM (latency hiding across the ldsm->mma chains).
// ---------------------------------------------------------------------------
#define STAGE_BYTES 32768          // A tile 16KB + B tile 16KB
#define GEMM_SMEM   (3 * STAGE_BYTES)

__global__ void __launch_bounds__(256, 2)
gemm_tf32_v3(const float* __restrict__ A, const float* __restrict__ Bw,
             const float* __restrict__ bias, float* __restrict__ C)
{
    extern __shared__ __align__(128) char dynsmem[];
    const uint32_t smemBase = (uint32_t)__cvta_generic_to_shared(dynsmem);

    const int tid  = threadIdx.x;
    const int lane = tid & 31;
    const int warp = tid >> 5;
    const int wm   = warp & 1;     // m offset wm*64
    const int wn   = warp >> 1;    // n offset wn*32
    const int rowBlk = blockIdx.y * 128;
    const int colBlk = blockIdx.x * 128;

    // per-thread cp.async chunk coords (4 chunks per tile per thread)
    int crow[4]; uint32_t csw[4];
#pragma unroll
    for (int i = 0; i < 4; i++) {
        int cid = tid + i * 256;        // 0..1023
        int r   = cid >> 3;
        int cc  = cid & 7;
        crow[i] = r;
        csw[i]  = r * 128 + ((cc ^ (r & 7)) << 4);
    }

    float acc[4][4][4];
#pragma unroll
    for (int mi = 0; mi < 4; mi++)
#pragma unroll
        for (int ni = 0; ni < 4; ni++)
#pragma unroll
            for (int q = 0; q < 4; q++) acc[mi][ni][q] = 0.f;

    const int aRowL = (lane & 15);
    const int aChL  = (lane >> 4);
    const int bRowL = ((lane >> 4) << 3) + (lane & 7);
    const int bChL  = ((lane >> 3) & 1);

    auto issue = [&](int ks, int stage) {
        uint32_t sA = smemBase + stage * STAGE_BYTES;
        uint32_t sB = sA + 16384;
        const float* Ag = A  + (size_t)rowBlk * EMB + ks * 32;
        const float* Bg = Bw + (size_t)colBlk * EMB + ks * 32;
#pragma unroll
        for (int i = 0; i < 4; i++) {
            int cc = (tid + i * 256) & 7;
            cpa16(sA + csw[i], Ag + (size_t)crow[i] * EMB + cc * 4);
            cpa16(sB + csw[i], Bg + (size_t)crow[i] * EMB + cc * 4);
        }
    };

    issue(0, 0); CP_COMMIT();
    issue(1, 1); CP_COMMIT();

#pragma unroll 1
    for (int ks = 0; ks < NKS; ks++) {
        if (ks + 2 < NKS) issue(ks + 2, (ks + 2) % 3);
        CP_COMMIT();
        CP_WAIT2();
        __syncthreads();

        uint32_t sA = smemBase + (ks % 3) * STAGE_BYTES;
        uint32_t sB = sA + 16384;

#pragma unroll
        for (int kt = 0; kt < 4; kt++) {
            uint32_t af[4][4];
            uint32_t bf[4][2];
#pragma unroll
            for (int mt = 0; mt < 4; mt++) {
                int r  = wm * 64 + mt * 16 + aRowL;
                int ch = 2 * kt + aChL;
                uint32_t addr = sA + r * 128 + ((ch ^ (r & 7)) << 4);
                ldsm4(af[mt][0], af[mt][1], af[mt][2], af[mt][3], addr);
            }
#pragma unroll
            for (int p = 0; p < 2; p++) {
                int r  = wn * 32 + p * 16 + bRowL;
                int ch = 2 * kt + bChL;
                uint32_t addr = sB + r * 128 + ((ch ^ (r & 7)) << 4);
                uint32_t t0, t1, t2, t3;
                ldsm4(t0, t1, t2, t3, addr);
                bf[2 * p][0] = t0; bf[2 * p][1] = t1;
                bf[2 * p + 1][0] = t2; bf[2 * p + 1][1] = t3;
            }
#pragma unroll
            for (int mi = 0; mi < 4; mi++)
#pragma unroll
                for (int ni = 0; ni < 4; ni++)
                    mma8(acc[mi][ni], af[mi], bf[ni]);
        }
        __syncthreads();
    }

    // ---- epilogue: bias + store ----
    const int g  = lane >> 2;
    const int tg = lane & 3;
#pragma unroll
    for (int mi = 0; mi < 4; mi++) {
        int r0 = rowBlk + wm * 64 + mi * 16 + g;
#pragma unroll
        for (int ni = 0; ni < 4; ni++) {
            int c0 = colBlk + wn * 32 + ni * 8 + tg * 2;
            float2 bb = *(const float2*)&bias[c0];
            float2 s0 = make_float2(acc[mi][ni][0] + bb.x, acc[mi][ni][1] + bb.y);
            float2 s1 = make_float2(acc[mi][ni][2] + bb.x, acc[mi][ni][3] + bb.y);
            *(float2*)&C[(size_t)r0 * EMB + c0]       = s0;
            *(float2*)&C[(size_t)(r0 + 8) * EMB + c0] = s1;
        }
    }
}

// ---------------------------------------------------------------------------
// Causal flash attention, packed f32x2 math (2 fp32 FMA per issue slot).
// 1 query/thread; K/V tiles in SMEM; output tf32-rounded for the O GEMM.
// ---------------------------------------------------------------------------
__global__ void __launch_bounds__(128)
attn_kernel(const float* __restrict__ Q, const float* __restrict__ K,
            const float* __restrict__ V, float* __restrict__ O)
{
    __shared__ __align__(16) float Ks[64][64];
    __shared__ __align__(16) float Vs[64][64];

    const int bh = blockIdx.y;
    const int b  = bh >> 4;
    const int h  = bh & 15;
    const int qi = blockIdx.x * 128 + threadIdx.x;

    const float* qptr = Q + ((size_t)(b * SEQ + qi)) * EMB + h * HDIM;
    u64 q2[32];
    {
        const u64* qp = (const u64*)qptr;
#pragma unroll
        for (int i = 0; i < 32; i++) q2[i] = qp[i];
    }

    u64 o2[32];
#pragma unroll
    for (int i = 0; i < 32; i++) o2[i] = 0ull;   // (0.f, 0.f)

    float m = -1e30f, l = 0.f;

    const float* Kbase = K + ((size_t)b * SEQ) * EMB + h * HDIM;
    const float* Vbase = V + ((size_t)b * SEQ) * EMB + h * HDIM;

    const int nTiles = blockIdx.x * 2 + 2;

    for (int t = 0; t < nTiles; t++) {
        const int base = t * 64;
        __syncthreads();
        for (int f = threadIdx.x; f < 64 * 16; f += 128) {
            int r = f >> 4;
            int c = f & 15;
            ((float4*)Ks[r])[c] = ((const float4*)(Kbase + (size_t)(base + r) * EMB))[c];
            ((float4*)Vs[r])[c] = ((const float4*)(Vbase + (size_t)(base + r) * EMB))[c];
        }
        __syncthreads();

#pragma unroll 1
        for (int sc = 0; sc < 4; sc++) {
            const int j0 = base + sc * 16;
            if (j0 > qi) break;

            float s[16];
#pragma unroll
            for (int j = 0; j < 16; j++) {
                const ulonglong2* kr = (const ulonglong2*)Ks[sc * 16 + j];
                u64 a0 = 0ull, a1 = 0ull;
#pragma unroll
                for (int i = 0; i < 16; i++) {
                    ulonglong2 kk = kr[i];
                    a0 = fma2(q2[2 * i],     kk.x, a0);
                    a1 = fma2(q2[2 * i + 1], kk.y, a1);
                }
                float x0, x1, y0, y1;
                unpack2(a0, x0, x1);
                unpack2(a1, y0, y1);
                float sv = ((x0 + y0) + (x1 + y1)) * ATTN_SCALE;
                s[j] = (j0 + j > qi) ? -1e30f : sv;
            }

            float cmax = s[0];
#pragma unroll
            for (int j = 1; j < 16; j++) cmax = fmaxf(cmax, s[j]);
            float mn   = fmaxf(m, cmax);
            float corr = __expf(m - mn);
            l *= corr;
            u64 c2 = pack2(corr, corr);
#pragma unroll
            for (int i = 0; i < 32; i++) o2[i] = mul2(o2[i], c2);
            m = mn;

#pragma unroll
            for (int j = 0; j < 16; j++) {
                float p = __expf(s[j] - mn);
                l += p;
                u64 p2 = pack2(p, p);
                const ulonglong2* vr = (const ulonglong2*)Vs[sc * 16 + j];
#pragma unroll
                for (int i = 0; i < 16; i++) {
                    ulonglong2 vv = vr[i];
                    o2[2 * i]     = fma2(p2, vv.x, o2[2 * i]);
                    o2[2 * i + 1] = fma2(p2, vv.y, o2[2 * i + 1]);
                }
            }
        }
    }

    const float inv = 1.f / l;
    const u64 i2 = pack2(inv, inv);
    float* optr = O + ((size_t)(b * SEQ + qi)) * EMB + h * HDIM;
#pragma unroll
    for (int i = 0; i < 16; i++) {
        u64 r0 = mul2(o2[2 * i], i2);
        u64 r1 = mul2(o2[2 * i + 1], i2);
        float a, bb, c, d;
        unpack2(r0, a, bb);
        unpack2(r1, c, d);
        float4 st;
        st.x = tf32r(a); st.y = tf32r(bb); st.z = tf32r(c); st.w = tf32r(d);
        ((float4*)optr)[i] = st;
    }
}

// ---------------------------------------------------------------------------
// Launch
// ---------------------------------------------------------------------------
extern "C" void kernel_launch(void* const* d_in, const int* in_sizes, int n_in,
                              void* d_out, int out_size)
{
    const float* xq = (const float*)d_in[0];
    const float* xk = (const float*)d_in[1];
    const float* xv = (const float*)d_in[2];
    // d_in[3] = mask (deterministic causal tril) — exploited structurally
    const float* Wq = (const float*)d_in[4];
    const float* bq = (const float*)d_in[5];
    const float* Wk = (const float*)d_in[6];
    const float* bk = (const float*)d_in[7];
    const float* Wv = (const float*)d_in[8];
    const float* bv = (const float*)d_in[9];
    const float* Wo = (const float*)d_in[10];
    const float* bo = (const float*)d_in[11];
    float* out = (float*)d_out;

    float *pQ, *pK, *pV, *pA, *pRX, *pRW;
    cudaGetSymbolAddress((void**)&pQ,  g_Q);
    cudaGetSymbolAddress((void**)&pK,  g_K);
    cudaGetSymbolAddress((void**)&pV,  g_V);
    cudaGetSymbolAddress((void**)&pA,  g_A);
    cudaGetSymbolAddress((void**)&pRX, g_RX);
    cudaGetSymbolAddress((void**)&pRW, g_RW);

    cudaFuncSetAttribute(gemm_tf32_v3,
                         cudaFuncAttributeMaxDynamicSharedMemorySize, GEMM_SMEM);

    dim3 ggrid(EMB / 128, MROWS / 128);   // (8, 32)
    const int rX = (MROWS * EMB / 4) / 256;
    const int rW = (EMB * EMB / 4) / 256;

    // Q projection
    round_tf32_kernel<<<rX, 256>>>((const float4*)xq, (float4*)pRX);
    round_tf32_kernel<<<rW, 256>>>((const float4*)Wq, (float4*)pRW);
    gemm_tf32_v3<<<ggrid, 256, GEMM_SMEM>>>(pRX, pRW, bq, pQ);
    // K projection
    round_tf32_kernel<<<rX, 256>>>((const float4*)xk, (float4*)pRX);
    round_tf32_kernel<<<rW, 256>>>((const float4*)Wk, (float4*)pRW);
    gemm_tf32_v3<<<ggrid, 256, GEMM_SMEM>>>(pRX, pRW, bk, pK);
    // V projection
    round_tf32_kernel<<<rX, 256>>>((const float4*)xv, (float4*)pRX);
    round_tf32_kernel<<<rW, 256>>>((const float4*)Wv, (float4*)pRW);
    gemm_tf32_v3<<<ggrid, 256, GEMM_SMEM>>>(pRX, pRW, bv, pV);

    // attention (writes tf32-rounded output)
    dim3 agrid(SEQ / 128, BATCH * NHEAD); // (16, 32)
    attn_kernel<<<agrid, 128>>>(pQ, pK, pV, pA);

    // O projection
    round_tf32_kernel<<<rW, 256>>>((const float4*)Wo, (float4*)pRW);
    gemm_tf32_v3<<<ggrid, 256, GEMM_SMEM>>>(pA, pRW, bo, out);
}